// round 2
// baseline (speedup 1.0000x reference)
#include <cuda_runtime.h>

#define MAXN 100000
#define MAXE 1600000

// ---------------- device scratch ----------------
__device__ __align__(16) int   g_deg[MAXN];
__device__ __align__(16) int   g_off[MAXN + 1];
__device__ __align__(16) int   g_cur[MAXN];
__device__ __align__(16) int   g_srcidx[MAXE];
__device__ __align__(16) int   g_part[1024];
__device__ __align__(16) float g_ya[MAXN * 64];
__device__ __align__(16) float g_yb[MAXN * 64];
__device__ __align__(16) float g_stats[3 * 2 * 64];
__device__ __align__(16) float g_scale[64];
__device__ __align__(16) float g_shift[64];
__device__ float g_sumexp;
__device__ __align__(16) float g_pool[64 * 64];
__device__ int   g_bcnt[64];
__device__ int   g_is64;

// ---------------- dtype detection (parallel, MLP=32) ----------------
__global__ void k_detect(const long long* __restrict__ ei, int n) {
    int lane = threadIdx.x;
    int bad = 0;
    for (int i = lane; i < 512; i += 32) {
        long long v = ei[i];
        bad |= (v < 0 || v >= (long long)n) ? 1 : 0;
    }
    bad = __any_sync(0xffffffffu, bad);
    if (lane == 0) g_is64 = bad ? 0 : 1;
}

__device__ __forceinline__ int load_idx(const void* p, int i) {
    if (g_is64) return (int)((const long long*)p)[i];
    return ((const int*)p)[i];
}

// ---------------- init ----------------
__global__ void k_zero(int n) {
    int i = blockIdx.x * blockDim.x + threadIdx.x;
    if (i < n) g_deg[i] = 0;
    if (i < 3 * 2 * 64) g_stats[i] = 0.f;
    if (i < 64 * 64) g_pool[i] = 0.f;
    if (i < 64) g_bcnt[i] = 0;
    if (i == 0) g_sumexp = 0.f;
}

// ---------------- CSR build ----------------
__global__ void k_hist(const void* __restrict__ ei, int e) {
    int i = blockIdx.x * blockDim.x + threadIdx.x;
    if (i >= e) return;
    int dst = load_idx(ei, e + i);
    atomicAdd(&g_deg[dst], 1);
}

__global__ void k_scan1(int n) {
    __shared__ int sh[1024];
    int t = threadIdx.x;
    int i = blockIdx.x * 1024 + t;
    int v = (i < n) ? g_deg[i] : 0;
    sh[t] = v; __syncthreads();
    for (int d = 512; d > 0; d >>= 1) {
        if (t < d) sh[t] += sh[t + d];
        __syncthreads();
    }
    if (t == 0) g_part[blockIdx.x] = sh[0];
}

__global__ void k_scan2(int nb, int n, int e) {
    __shared__ int sh[1024];
    int t = threadIdx.x;
    int v = (t < nb) ? g_part[t] : 0;
    sh[t] = v; __syncthreads();
    for (int d = 1; d < 1024; d <<= 1) {
        int add = (t >= d) ? sh[t - d] : 0;
        __syncthreads();
        sh[t] += add;
        __syncthreads();
    }
    if (t < nb) g_part[t] = sh[t] - v;
    if (t == 0) g_off[n] = e;
}

__global__ void k_scan3(int n) {
    __shared__ int sh[1024];
    int t = threadIdx.x;
    int i = blockIdx.x * 1024 + t;
    int v = (i < n) ? g_deg[i] : 0;
    sh[t] = v; __syncthreads();
    for (int d = 1; d < 1024; d <<= 1) {
        int add = (t >= d) ? sh[t - d] : 0;
        __syncthreads();
        sh[t] += add;
        __syncthreads();
    }
    int excl = sh[t] - v + g_part[blockIdx.x];
    if (i < n) { g_off[i] = excl; g_cur[i] = excl; }
}

__global__ void k_scatter(const void* __restrict__ ei, int e) {
    int i = blockIdx.x * blockDim.x + threadIdx.x;
    if (i >= e) return;
    int src = load_idx(ei, i);
    int dst = load_idx(ei, e + i);
    int pos = atomicAdd(&g_cur[dst], 1);
    g_srcidx[pos] = src;
}

// ---------------- fused layer: agg(+BN-on-read) -> mm -> stats ----------------
// Block = 256 threads = 8 warps = 64 nodes. Warp aggregates 8 nodes (lane = 2 ch),
// stages BN'd self-features, then does y = agg@Wl + h@Wr + b with weights in smem.
template <int DIN, bool BN_IN>
__global__ void __launch_bounds__(256, 2)
k_layer(const float* __restrict__ in,
        const float* __restrict__ Wl, const float* __restrict__ Wr,
        const float* __restrict__ bias,
        const float* __restrict__ scale, const float* __restrict__ shift,
        float* __restrict__ yout, float* __restrict__ stats, int n) {
    constexpr int DP = (DIN == 6) ? 8 : 64;
    extern __shared__ float sm[];
    float* sWl  = sm;                       // DIN*64
    float* sWr  = sWl + DIN * 64;           // DIN*64
    float* sAgg = sWr + DIN * 64;           // 64*DP
    float* sH   = sAgg + 64 * DP;           // 64*DP
    float* sb   = sH + 64 * DP;             // 64
    float* redS = sb + 64;                  // 512
    float* redQ = redS + 512;               // 512

    int tid = threadIdx.x;
    for (int i = tid; i < DIN * 64; i += 256) { sWl[i] = Wl[i]; sWr[i] = Wr[i]; }
    if (tid < 64) sb[tid] = bias[tid];

    int warp = tid >> 5, lane = tid & 31;
    int base = blockIdx.x * 64;
    int c0 = lane * 2;

    // ---- phase 1: aggregation ----
    if (DIN == 64) {
        float bnsc0 = 1.f, bnsc1 = 1.f, bnsh0 = 0.f, bnsh1 = 0.f;
        if (BN_IN) {
            bnsc0 = __ldg(&scale[c0]); bnsc1 = __ldg(&scale[c0 + 1]);
            bnsh0 = __ldg(&shift[c0]); bnsh1 = __ldg(&shift[c0 + 1]);
        }
        const float2* hp = (const float2*)in;
#pragma unroll 1
        for (int j = 0; j < 8; j++) {
            int node = base + warp * 8 + j;
            float ax = 0.f, ay = 0.f;
            int deg = 0;
            if (node < n) {
                int s = g_off[node], t = g_off[node + 1];
                deg = t - s;
                int e = s;
                for (; e + 4 <= t; e += 4) {
                    int i0 = g_srcidx[e], i1 = g_srcidx[e + 1];
                    int i2 = g_srcidx[e + 2], i3 = g_srcidx[e + 3];
                    float2 v0 = __ldg(&hp[i0 * 32 + lane]);
                    float2 v1 = __ldg(&hp[i1 * 32 + lane]);
                    float2 v2 = __ldg(&hp[i2 * 32 + lane]);
                    float2 v3 = __ldg(&hp[i3 * 32 + lane]);
                    if (BN_IN) {
                        v0.x = fmaxf(fmaf(v0.x, bnsc0, bnsh0), 0.f);
                        v0.y = fmaxf(fmaf(v0.y, bnsc1, bnsh1), 0.f);
                        v1.x = fmaxf(fmaf(v1.x, bnsc0, bnsh0), 0.f);
                        v1.y = fmaxf(fmaf(v1.y, bnsc1, bnsh1), 0.f);
                        v2.x = fmaxf(fmaf(v2.x, bnsc0, bnsh0), 0.f);
                        v2.y = fmaxf(fmaf(v2.y, bnsc1, bnsh1), 0.f);
                        v3.x = fmaxf(fmaf(v3.x, bnsc0, bnsh0), 0.f);
                        v3.y = fmaxf(fmaf(v3.y, bnsc1, bnsh1), 0.f);
                    }
                    ax += (v0.x + v1.x) + (v2.x + v3.x);
                    ay += (v0.y + v1.y) + (v2.y + v3.y);
                }
                for (; e < t; e++) {
                    int i0 = g_srcidx[e];
                    float2 v0 = __ldg(&hp[i0 * 32 + lane]);
                    if (BN_IN) {
                        v0.x = fmaxf(fmaf(v0.x, bnsc0, bnsh0), 0.f);
                        v0.y = fmaxf(fmaf(v0.y, bnsc1, bnsh1), 0.f);
                    }
                    ax += v0.x; ay += v0.y;
                }
            }
            float inv = 1.f / fmaxf((float)deg, 1.f);
            sAgg[(warp * 8 + j) * 64 + c0]     = ax * inv;
            sAgg[(warp * 8 + j) * 64 + c0 + 1] = ay * inv;
        }
        // stage BN'd self features
        for (int i = tid; i < 64 * 16; i += 256) {
            int j = i >> 4; int c = (i & 15) * 4;
            int node = base + j;
            float4 v = make_float4(0.f, 0.f, 0.f, 0.f);
            if (node < n) {
                v = *(const float4*)&in[node * 64 + c];
                if (BN_IN) {
                    v.x = fmaxf(fmaf(v.x, __ldg(&scale[c]),     __ldg(&shift[c])),     0.f);
                    v.y = fmaxf(fmaf(v.y, __ldg(&scale[c + 1]), __ldg(&shift[c + 1])), 0.f);
                    v.z = fmaxf(fmaf(v.z, __ldg(&scale[c + 2]), __ldg(&shift[c + 2])), 0.f);
                    v.w = fmaxf(fmaf(v.w, __ldg(&scale[c + 3]), __ldg(&shift[c + 3])), 0.f);
                }
            }
            *(float4*)&sH[j * 64 + c] = v;
        }
    } else {
        // DIN == 6, layer 1: lanes 0..5 = channels
#pragma unroll 1
        for (int j = 0; j < 8; j++) {
            int node = base + warp * 8 + j;
            float acc = 0.f;
            int deg = 0;
            if (node < n) {
                int s = g_off[node], t = g_off[node + 1];
                deg = t - s;
                int e = s;
                for (; e + 4 <= t; e += 4) {
                    int i0 = g_srcidx[e], i1 = g_srcidx[e + 1];
                    int i2 = g_srcidx[e + 2], i3 = g_srcidx[e + 3];
                    if (lane < 6) {
                        float a0 = __ldg(&in[i0 * 6 + lane]);
                        float a1 = __ldg(&in[i1 * 6 + lane]);
                        float a2 = __ldg(&in[i2 * 6 + lane]);
                        float a3 = __ldg(&in[i3 * 6 + lane]);
                        acc += (a0 + a1) + (a2 + a3);
                    }
                }
                for (; e < t; e++) {
                    if (lane < 6) acc += __ldg(&in[g_srcidx[e] * 6 + lane]);
                }
            }
            if (lane < 8)
                sAgg[(warp * 8 + j) * 8 + lane] =
                    (lane < 6) ? acc / fmaxf((float)deg, 1.f) : 0.f;
        }
        for (int i = tid; i < 64 * 8; i += 256) {
            int j = i >> 3; int c = i & 7;
            int node = base + j;
            sH[i] = (node < n && c < 6) ? __ldg(&in[node * 6 + c]) : 0.f;
        }
    }
    __syncthreads();

    // ---- phase 2: dense matmul ----
    float y[8][2];
#pragma unroll
    for (int j = 0; j < 8; j++) { y[j][0] = sb[c0]; y[j][1] = sb[c0 + 1]; }

    if (DIN == 64) {
#pragma unroll 2
        for (int k = 0; k < 64; k += 4) {
            float2 wl0 = *(float2*)&sWl[(k + 0) * 64 + c0];
            float2 wl1 = *(float2*)&sWl[(k + 1) * 64 + c0];
            float2 wl2 = *(float2*)&sWl[(k + 2) * 64 + c0];
            float2 wl3 = *(float2*)&sWl[(k + 3) * 64 + c0];
            float2 wr0 = *(float2*)&sWr[(k + 0) * 64 + c0];
            float2 wr1 = *(float2*)&sWr[(k + 1) * 64 + c0];
            float2 wr2 = *(float2*)&sWr[(k + 2) * 64 + c0];
            float2 wr3 = *(float2*)&sWr[(k + 3) * 64 + c0];
#pragma unroll
            for (int j = 0; j < 8; j++) {
                float4 a = *(const float4*)&sAgg[(warp * 8 + j) * 64 + k];
                float4 h = *(const float4*)&sH[(warp * 8 + j) * 64 + k];
                y[j][0] += a.x * wl0.x + a.y * wl1.x + a.z * wl2.x + a.w * wl3.x
                         + h.x * wr0.x + h.y * wr1.x + h.z * wr2.x + h.w * wr3.x;
                y[j][1] += a.x * wl0.y + a.y * wl1.y + a.z * wl2.y + a.w * wl3.y
                         + h.x * wr0.y + h.y * wr1.y + h.z * wr2.y + h.w * wr3.y;
            }
        }
    } else {
#pragma unroll
        for (int k = 0; k < 6; k++) {
            float2 wl = *(float2*)&sWl[k * 64 + c0];
            float2 wr = *(float2*)&sWr[k * 64 + c0];
#pragma unroll
            for (int j = 0; j < 8; j++) {
                float a = sAgg[(warp * 8 + j) * 8 + k];
                float h = sH[(warp * 8 + j) * 8 + k];
                y[j][0] += a * wl.x + h * wr.x;
                y[j][1] += a * wl.y + h * wr.y;
            }
        }
    }

    // ---- phase 3: store + BN stats ----
    float ls0 = 0.f, ls1 = 0.f, lq0 = 0.f, lq1 = 0.f;
#pragma unroll
    for (int j = 0; j < 8; j++) {
        int node = base + warp * 8 + j;
        if (node < n) {
            float v0 = y[j][0], v1 = y[j][1];
            float2 o; o.x = v0; o.y = v1;
            *(float2*)&yout[node * 64 + c0] = o;
            ls0 += v0; lq0 += v0 * v0;
            ls1 += v1; lq1 += v1 * v1;
        }
    }
    redS[warp * 64 + c0] = ls0; redS[warp * 64 + c0 + 1] = ls1;
    redQ[warp * 64 + c0] = lq0; redQ[warp * 64 + c0 + 1] = lq1;
    __syncthreads();
    if (tid < 64) {
        float s = 0.f, q = 0.f;
#pragma unroll
        for (int w2 = 0; w2 < 8; w2++) { s += redS[w2 * 64 + tid]; q += redQ[w2 * 64 + tid]; }
        atomicAdd(&stats[tid], s);
        atomicAdd(&stats[64 + tid], q);
    }
}

// ---------------- BN finalize ----------------
__global__ void k_bnfin(const float* __restrict__ stats,
                        const float* __restrict__ g, const float* __restrict__ be,
                        float invn) {
    int c = threadIdx.x;
    float mu = stats[c] * invn;
    float var = stats[64 + c] * invn - mu * mu;
    float rstd = rsqrtf(var + 1e-5f);
    float sc = rstd * g[c];
    g_scale[c] = sc;
    g_shift[c] = be[c] - mu * sc;
}

// ---------------- pooling ----------------
__global__ void k_prepool(const float* __restrict__ x, const void* __restrict__ batch, int n) {
    __shared__ float ssum[256];
    __shared__ int hist[64];
    int tid = threadIdx.x;
    if (tid < 64) hist[tid] = 0;
    __syncthreads();
    int i = blockIdx.x * blockDim.x + tid;
    float loc = 0.f;
    if (i < n) {
        loc = expf(__ldg(&x[i * 6 + 4]));
        atomicAdd(&hist[load_idx(batch, i)], 1);
    }
    ssum[tid] = loc; __syncthreads();
    for (int d = 128; d > 0; d >>= 1) {
        if (tid < d) ssum[tid] += ssum[tid + d];
        __syncthreads();
    }
    if (tid == 0) atomicAdd(&g_sumexp, ssum[0]);
    if (tid < 64 && hist[tid]) atomicAdd(&g_bcnt[tid], hist[tid]);
}

// 64 nodes/block, 64 threads (= channels). BN3 applied on read. Fast path when
// the whole block is one batch segment (common: segments avg ~1563 nodes).
__global__ void k_pool(const void* __restrict__ batch, const float* __restrict__ x,
                       const float* __restrict__ y3,
                       const float* __restrict__ scale, const float* __restrict__ shift, int n) {
    __shared__ float w[64];
    __shared__ int bb[64];
    int tid = threadIdx.x;
    int base = blockIdx.x * 64;
    float S = g_sumexp;
    {
        int i = base + tid;
        if (i < n) { w[tid] = expf(__ldg(&x[i * 6 + 4])) / S; bb[tid] = load_idx(batch, i); }
        else { w[tid] = 0.f; bb[tid] = -1; }
    }
    __syncthreads();
    int m = n - base; if (m > 64) m = 64;
    float sc = scale[tid], sh = shift[tid];
    if (m == 64 && bb[0] == bb[63]) {
        float a0 = 0.f, a1 = 0.f, a2 = 0.f, a3 = 0.f;
        for (int j = 0; j < 64; j += 4) {
            float h0 = fmaxf(fmaf(__ldg(&y3[(base + j + 0) * 64 + tid]), sc, sh), 0.f);
            float h1 = fmaxf(fmaf(__ldg(&y3[(base + j + 1) * 64 + tid]), sc, sh), 0.f);
            float h2 = fmaxf(fmaf(__ldg(&y3[(base + j + 2) * 64 + tid]), sc, sh), 0.f);
            float h3 = fmaxf(fmaf(__ldg(&y3[(base + j + 3) * 64 + tid]), sc, sh), 0.f);
            a0 += w[j] * h0; a1 += w[j + 1] * h1; a2 += w[j + 2] * h2; a3 += w[j + 3] * h3;
        }
        atomicAdd(&g_pool[bb[0] * 64 + tid], (a0 + a1) + (a2 + a3));
    } else {
        float acc = 0.f;
        int cur = bb[0];
        for (int j = 0; j < m; j++) {
            int b = bb[j];
            if (b != cur) {
                if (cur >= 0) atomicAdd(&g_pool[cur * 64 + tid], acc);
                acc = 0.f; cur = b;
            }
            acc += w[j] * fmaxf(fmaf(__ldg(&y3[(base + j) * 64 + tid]), sc, sh), 0.f);
        }
        if (cur >= 0 && m > 0) atomicAdd(&g_pool[cur * 64 + tid], acc);
    }
}

// ---------------- heads ----------------
__global__ void k_head(const float* __restrict__ phW1, const float* __restrict__ phb1,
                       const float* __restrict__ phW2, const float* __restrict__ phb2,
                       const float* __restrict__ trW1, const float* __restrict__ trb1,
                       const float* __restrict__ trW2, const float* __restrict__ trb2,
                       float* __restrict__ out) {
    __shared__ float pool[64 * 64];
    __shared__ float hid[64 * 32];
    __shared__ float hidt[64 * 16];
    int tid = threadIdx.x;
    for (int i = tid; i < 64 * 64; i += 256) {
        int b = i >> 6;
        float c = (float)g_bcnt[b];
        pool[i] = g_pool[i] / fmaxf(c, 1.f);
    }
    __syncthreads();
    for (int i = tid; i < 64 * 32; i += 256) {
        int b = i >> 5, j = i & 31;
        float s = phb1[j];
        for (int k = 0; k < 64; k++) s += pool[b * 64 + k] * phW1[k * 32 + j];
        hid[i] = fmaxf(s, 0.f);
    }
    for (int i = tid; i < 64 * 16; i += 256) {
        int b = i >> 4, j = i & 15;
        float s = trb1[j];
        for (int k = 0; k < 64; k++) s += pool[b * 64 + k] * trW1[k * 16 + j];
        hidt[i] = fmaxf(s, 0.f);
    }
    __syncthreads();
    for (int i = tid; i < 64 * 3; i += 256) {
        int b = i / 3, j = i - b * 3;
        float s = phb2[j];
        for (int k = 0; k < 32; k++) s += hid[b * 32 + k] * phW2[k * 3 + j];
        out[i] = s;
    }
    for (int i = tid; i < 64; i += 256) {
        float s = trb2[0];
        for (int k = 0; k < 16; k++) s += hidt[i * 16 + k] * trW2[k];
        out[192 + i] = 1.f / (1.f + expf(-s));
    }
}

// ---------------- launch ----------------
extern "C" void kernel_launch(void* const* d_in, const int* in_sizes, int n_in,
                              void* d_out, int out_size) {
    const float* x   = (const float*)d_in[0];
    const void*  ei  = d_in[1];
    const void*  bat = d_in[2];
    const float* W1l = (const float*)d_in[3];
    const float* b1  = (const float*)d_in[4];
    const float* W1r = (const float*)d_in[5];
    const float* W2l = (const float*)d_in[6];
    const float* b2  = (const float*)d_in[7];
    const float* W2r = (const float*)d_in[8];
    const float* W3l = (const float*)d_in[9];
    const float* b3  = (const float*)d_in[10];
    const float* W3r = (const float*)d_in[11];
    const float* g1  = (const float*)d_in[12];
    const float* be1 = (const float*)d_in[13];
    const float* g2  = (const float*)d_in[14];
    const float* be2 = (const float*)d_in[15];
    const float* g3  = (const float*)d_in[16];
    const float* be3 = (const float*)d_in[17];
    const float* phW1 = (const float*)d_in[18];
    const float* phb1 = (const float*)d_in[19];
    const float* phW2 = (const float*)d_in[20];
    const float* phb2 = (const float*)d_in[21];
    const float* trW1 = (const float*)d_in[22];
    const float* trb1 = (const float*)d_in[23];
    const float* trW2 = (const float*)d_in[24];
    const float* trb2 = (const float*)d_in[25];
    float* out = (float*)d_out;

    int n = in_sizes[0] / 6;
    int e = in_sizes[1] / 2;

    float *p_ya, *p_yb, *p_stats, *p_scale, *p_shift;
    cudaGetSymbolAddress((void**)&p_ya, g_ya);
    cudaGetSymbolAddress((void**)&p_yb, g_yb);
    cudaGetSymbolAddress((void**)&p_stats, g_stats);
    cudaGetSymbolAddress((void**)&p_scale, g_scale);
    cudaGetSymbolAddress((void**)&p_shift, g_shift);

    const int SMEM64 = (2 * 64 * 64 + 2 * 64 * 64 + 64 + 1024) * 4;  // 69,888 B
    const int SMEM6  = (2 * 6 * 64 + 2 * 64 * 8 + 64 + 1024) * 4;    // 11,520 B
    cudaFuncSetAttribute(k_layer<64, true>, cudaFuncAttributeMaxDynamicSharedMemorySize, SMEM64);

    // detect + init + CSR
    k_detect<<<1, 32>>>((const long long*)ei, n);
    k_zero<<<(n + 255) / 256, 256>>>(n);
    k_hist<<<(e + 255) / 256, 256>>>(ei, e);
    int nb = (n + 1023) / 1024;
    k_scan1<<<nb, 1024>>>(n);
    k_scan2<<<1, 1024>>>(nb, n, e);
    k_scan3<<<nb, 1024>>>(n);
    k_scatter<<<(e + 255) / 256, 256>>>(ei, e);

    int nodeBlocks = (n + 63) / 64;

    // layer 1 (input = x, no BN on read)
    k_layer<6, false><<<nodeBlocks, 256, SMEM6>>>(x, W1l, W1r, b1, nullptr, nullptr,
                                                  p_ya, p_stats + 0 * 128, n);
    k_bnfin<<<1, 64>>>(p_stats + 0 * 128, g1, be1, 1.f / (float)n);

    // layer 2 (reads ya with BN1 applied on the fly, writes yb)
    k_layer<64, true><<<nodeBlocks, 256, SMEM64>>>(p_ya, W2l, W2r, b2, p_scale, p_shift,
                                                   p_yb, p_stats + 1 * 128, n);
    k_bnfin<<<1, 64>>>(p_stats + 1 * 128, g2, be2, 1.f / (float)n);

    // layer 3 (reads yb with BN2, writes ya)
    k_layer<64, true><<<nodeBlocks, 256, SMEM64>>>(p_yb, W3l, W3r, b3, p_scale, p_shift,
                                                   p_ya, p_stats + 2 * 128, n);
    k_bnfin<<<1, 64>>>(p_stats + 2 * 128, g3, be3, 1.f / (float)n);

    // pooling (BN3 applied on read) + heads
    k_prepool<<<(n + 255) / 256, 256>>>(x, bat, n);
    k_pool<<<nodeBlocks, 64>>>(bat, x, p_ya, p_scale, p_shift, n);
    k_head<<<1, 256>>>(phW1, phb1, phW2, phb2, trW1, trb1, trW2, trb2, out);
}

// round 3
// speedup vs baseline: 1.7156x; 1.7156x over previous
#include <cuda_runtime.h>

#define MAXN 100000
#define MAXE 1600000
#define HIDC 64
#define NB 64

// ---------------- device scratch ----------------
__device__ __align__(16) int   g_deg[MAXN];
__device__ __align__(16) int   g_off[MAXN + 1];
__device__ __align__(16) int   g_cur[MAXN];
__device__ __align__(16) int   g_srcidx[MAXE];
__device__ __align__(16) int   g_part[1024];
__device__ __align__(16) float g_h[MAXN * HIDC];
__device__ __align__(16) float g_y[MAXN * HIDC];
__device__ __align__(16) float g_agg[MAXN * HIDC];
__device__ __align__(16) float g_agg6[MAXN * 8];
__device__ __align__(16) float g_stats[3 * 2 * HIDC];
__device__ __align__(16) float g_scale[HIDC];
__device__ __align__(16) float g_shift[HIDC];
__device__ float g_sumexp;
__device__ __align__(16) float g_pool[NB * HIDC];
__device__ int   g_bcnt[NB];
__device__ int   g_is64;

// ---------------- dtype detection (parallel, MLP=32) ----------------
__global__ void k_detect(const long long* __restrict__ ei, int n) {
    int lane = threadIdx.x;
    int bad = 0;
    for (int i = lane; i < 512; i += 32) {
        long long v = ei[i];
        bad |= (v < 0 || v >= (long long)n) ? 1 : 0;
    }
    bad = __any_sync(0xffffffffu, bad);
    if (lane == 0) g_is64 = bad ? 0 : 1;
}

__device__ __forceinline__ int load_idx(const void* p, int i) {
    if (g_is64) return (int)((const long long*)p)[i];
    return ((const int*)p)[i];
}

// ---------------- init ----------------
__global__ void k_zero(int n) {
    int i = blockIdx.x * blockDim.x + threadIdx.x;
    if (i < n) g_deg[i] = 0;
    if (i < 3 * 2 * HIDC) g_stats[i] = 0.f;
    if (i < NB * HIDC) g_pool[i] = 0.f;
    if (i < NB) g_bcnt[i] = 0;
    if (i == 0) g_sumexp = 0.f;
}

// ---------------- CSR build ----------------
__global__ void k_hist(const void* __restrict__ ei, int e) {
    int i = blockIdx.x * blockDim.x + threadIdx.x;
    if (i >= e) return;
    int dst = load_idx(ei, e + i);
    atomicAdd(&g_deg[dst], 1);
}

__global__ void k_scan1(int n) {
    __shared__ int sh[1024];
    int t = threadIdx.x;
    int i = blockIdx.x * 1024 + t;
    int v = (i < n) ? g_deg[i] : 0;
    sh[t] = v; __syncthreads();
    for (int d = 512; d > 0; d >>= 1) {
        if (t < d) sh[t] += sh[t + d];
        __syncthreads();
    }
    if (t == 0) g_part[blockIdx.x] = sh[0];
}

__global__ void k_scan2(int nb, int n, int e) {
    __shared__ int sh[1024];
    int t = threadIdx.x;
    int v = (t < nb) ? g_part[t] : 0;
    sh[t] = v; __syncthreads();
    for (int d = 1; d < 1024; d <<= 1) {
        int add = (t >= d) ? sh[t - d] : 0;
        __syncthreads();
        sh[t] += add;
        __syncthreads();
    }
    if (t < nb) g_part[t] = sh[t] - v;
    if (t == 0) g_off[n] = e;
}

__global__ void k_scan3(int n) {
    __shared__ int sh[1024];
    int t = threadIdx.x;
    int i = blockIdx.x * 1024 + t;
    int v = (i < n) ? g_deg[i] : 0;
    sh[t] = v; __syncthreads();
    for (int d = 1; d < 1024; d <<= 1) {
        int add = (t >= d) ? sh[t - d] : 0;
        __syncthreads();
        sh[t] += add;
        __syncthreads();
    }
    int excl = sh[t] - v + g_part[blockIdx.x];
    if (i < n) { g_off[i] = excl; g_cur[i] = excl; }
}

__global__ void k_scatter(const void* __restrict__ ei, int e) {
    int i = blockIdx.x * blockDim.x + threadIdx.x;
    if (i >= e) return;
    int src = load_idx(ei, i);
    int dst = load_idx(ei, e + i);
    int pos = atomicAdd(&g_cur[dst], 1);
    g_srcidx[pos] = src;
}

// ---------------- aggregation ----------------
// layer 1: 6-channel gather, one warp per node, lanes 0..5 = channels, MLP=4
__global__ void k_agg6(const float* __restrict__ x, int n) {
    int w = (blockIdx.x * blockDim.x + threadIdx.x) >> 5;
    int lane = threadIdx.x & 31;
    if (w >= n) return;
    int s = g_off[w], t = g_off[w + 1];
    float acc = 0.f;
    int e = s;
    for (; e + 4 <= t; e += 4) {
        int i0 = __ldg(&g_srcidx[e]);
        int i1 = __ldg(&g_srcidx[e + 1]);
        int i2 = __ldg(&g_srcidx[e + 2]);
        int i3 = __ldg(&g_srcidx[e + 3]);
        if (lane < 6) {
            float a0 = __ldg(&x[i0 * 6 + lane]);
            float a1 = __ldg(&x[i1 * 6 + lane]);
            float a2 = __ldg(&x[i2 * 6 + lane]);
            float a3 = __ldg(&x[i3 * 6 + lane]);
            acc += (a0 + a1) + (a2 + a3);
        }
    }
    for (; e < t; e++) {
        int i0 = __ldg(&g_srcidx[e]);
        if (lane < 6) acc += __ldg(&x[i0 * 6 + lane]);
    }
    float inv = 1.f / fmaxf((float)(t - s), 1.f);
    if (lane < 8) g_agg6[w * 8 + lane] = (lane < 6) ? acc * inv : 0.f;
}

// layers 2/3: 64-channel gather, one warp per node, lane = 2 channels, MLP=4
__global__ void k_agg64(const float* __restrict__ hin, int n) {
    int w = (blockIdx.x * blockDim.x + threadIdx.x) >> 5;
    int lane = threadIdx.x & 31;
    if (w >= n) return;
    int s = g_off[w], t = g_off[w + 1];
    float ax = 0.f, ay = 0.f;
    const float2* hp = (const float2*)hin;
    int e = s;
    for (; e + 4 <= t; e += 4) {
        int i0 = __ldg(&g_srcidx[e]);
        int i1 = __ldg(&g_srcidx[e + 1]);
        int i2 = __ldg(&g_srcidx[e + 2]);
        int i3 = __ldg(&g_srcidx[e + 3]);
        float2 v0 = __ldg(&hp[i0 * 32 + lane]);
        float2 v1 = __ldg(&hp[i1 * 32 + lane]);
        float2 v2 = __ldg(&hp[i2 * 32 + lane]);
        float2 v3 = __ldg(&hp[i3 * 32 + lane]);
        ax += (v0.x + v1.x) + (v2.x + v3.x);
        ay += (v0.y + v1.y) + (v2.y + v3.y);
    }
    for (; e < t; e++) {
        int i0 = __ldg(&g_srcidx[e]);
        float2 v = __ldg(&hp[i0 * 32 + lane]);
        ax += v.x; ay += v.y;
    }
    float inv = 1.f / fmaxf((float)(t - s), 1.f);
    float2 o; o.x = ax * inv; o.y = ay * inv;
    ((float2*)g_agg)[w * 32 + lane] = o;
}

// ---------------- per-node dense matmul + BN-stats ----------------
template <int DIN, int SA, int SH>
__global__ void __launch_bounds__(256)
k_mm(const float* __restrict__ aggin, const float* __restrict__ hin,
     const float* __restrict__ Wl, const float* __restrict__ Wr,
     const float* __restrict__ bias, float* __restrict__ stats, int n) {
    __shared__ float sWl[DIN * 64];
    __shared__ float sWr[DIN * 64];
    __shared__ float sb[64];
    __shared__ float redS[8][64];
    __shared__ float redQ[8][64];
    int tid = threadIdx.x;
    for (int i = tid; i < DIN * 64; i += 256) { sWl[i] = Wl[i]; sWr[i] = Wr[i]; }
    if (tid < 64) sb[tid] = bias[tid];
    __syncthreads();

    int warp = tid >> 5, lane = tid & 31;
    int c0 = lane * 2;
    int base = (blockIdx.x * 8 + warp) * 8;

    float y[8][2];
#pragma unroll
    for (int j = 0; j < 8; j++) { y[j][0] = sb[c0]; y[j][1] = sb[c0 + 1]; }

    if (DIN == 64) {
#pragma unroll 4
        for (int k = 0; k < 64; k += 4) {
            float2 wl0 = *(float2*)&sWl[(k + 0) * 64 + c0];
            float2 wl1 = *(float2*)&sWl[(k + 1) * 64 + c0];
            float2 wl2 = *(float2*)&sWl[(k + 2) * 64 + c0];
            float2 wl3 = *(float2*)&sWl[(k + 3) * 64 + c0];
            float2 wr0 = *(float2*)&sWr[(k + 0) * 64 + c0];
            float2 wr1 = *(float2*)&sWr[(k + 1) * 64 + c0];
            float2 wr2 = *(float2*)&sWr[(k + 2) * 64 + c0];
            float2 wr3 = *(float2*)&sWr[(k + 3) * 64 + c0];
#pragma unroll
            for (int j = 0; j < 8; j++) {
                int node = base + j; if (node >= n) node = n - 1;
                float4 a = *(const float4*)&aggin[node * SA + k];
                float4 h = *(const float4*)&hin[node * SH + k];
                y[j][0] += a.x * wl0.x + a.y * wl1.x + a.z * wl2.x + a.w * wl3.x
                         + h.x * wr0.x + h.y * wr1.x + h.z * wr2.x + h.w * wr3.x;
                y[j][1] += a.x * wl0.y + a.y * wl1.y + a.z * wl2.y + a.w * wl3.y
                         + h.x * wr0.y + h.y * wr1.y + h.z * wr2.y + h.w * wr3.y;
            }
        }
    } else {
#pragma unroll
        for (int k = 0; k < DIN; k++) {
            float2 wl = *(float2*)&sWl[k * 64 + c0];
            float2 wr = *(float2*)&sWr[k * 64 + c0];
#pragma unroll
            for (int j = 0; j < 8; j++) {
                int node = base + j; if (node >= n) node = n - 1;
                float a = __ldg(&aggin[node * SA + k]);
                float h = __ldg(&hin[node * SH + k]);
                y[j][0] += a * wl.x + h * wr.x;
                y[j][1] += a * wl.y + h * wr.y;
            }
        }
    }

    float ls0 = 0.f, ls1 = 0.f, lq0 = 0.f, lq1 = 0.f;
#pragma unroll
    for (int j = 0; j < 8; j++) {
        int node = base + j;
        if (node < n) {
            float v0 = y[j][0], v1 = y[j][1];
            float2 o; o.x = v0; o.y = v1;
            *(float2*)&g_y[node * 64 + c0] = o;
            ls0 += v0; lq0 += v0 * v0;
            ls1 += v1; lq1 += v1 * v1;
        }
    }
    redS[warp][c0] = ls0; redS[warp][c0 + 1] = ls1;
    redQ[warp][c0] = lq0; redQ[warp][c0 + 1] = lq1;
    __syncthreads();
    if (tid < 64) {
        float s = 0.f, q = 0.f;
#pragma unroll
        for (int w2 = 0; w2 < 8; w2++) { s += redS[w2][tid]; q += redQ[w2][tid]; }
        atomicAdd(&stats[tid], s);
        atomicAdd(&stats[64 + tid], q);
    }
}

// ---------------- BN finalize + apply ----------------
__global__ void k_bnfin(const float* __restrict__ stats,
                        const float* __restrict__ g, const float* __restrict__ be,
                        float invn) {
    int c = threadIdx.x;
    float mu = stats[c] * invn;
    float var = stats[64 + c] * invn - mu * mu;
    float rstd = rsqrtf(var + 1e-5f);
    float sc = rstd * g[c];
    g_scale[c] = sc;
    g_shift[c] = be[c] - mu * sc;
}

__global__ void k_bnapply(int n) {
    int i = blockIdx.x * blockDim.x + threadIdx.x;  // over n*16 float4s
    if (i >= n * 16) return;
    float4 v = *(const float4*)&g_y[i * 4];
    int c = (i & 15) * 4;
    float4 sc = *(const float4*)&g_scale[c];
    float4 sh = *(const float4*)&g_shift[c];
    v.x = fmaxf(fmaf(v.x, sc.x, sh.x), 0.f);
    v.y = fmaxf(fmaf(v.y, sc.y, sh.y), 0.f);
    v.z = fmaxf(fmaf(v.z, sc.z, sh.z), 0.f);
    v.w = fmaxf(fmaf(v.w, sc.w, sh.w), 0.f);
    *(float4*)&g_h[i * 4] = v;
}

// ---------------- pooling ----------------
__global__ void k_prepool(const float* __restrict__ x, const void* __restrict__ batch, int n) {
    __shared__ float ssum[256];
    __shared__ int hist[64];
    int tid = threadIdx.x;
    if (tid < 64) hist[tid] = 0;
    __syncthreads();
    int i = blockIdx.x * blockDim.x + tid;
    float loc = 0.f;
    if (i < n) {
        loc = expf(__ldg(&x[i * 6 + 4]));
        atomicAdd(&hist[load_idx(batch, i)], 1);
    }
    ssum[tid] = loc; __syncthreads();
    for (int d = 128; d > 0; d >>= 1) {
        if (tid < d) ssum[tid] += ssum[tid + d];
        __syncthreads();
    }
    if (tid == 0) atomicAdd(&g_sumexp, ssum[0]);
    if (tid < 64 && hist[tid]) atomicAdd(&g_bcnt[tid], hist[tid]);
}

// 64 nodes/block, 64 threads (= channels). Fast path (MLP=4) when block is one segment.
__global__ void k_pool(const void* __restrict__ batch, const float* __restrict__ x, int n) {
    __shared__ float w[64];
    __shared__ int bb[64];
    int tid = threadIdx.x;
    int base = blockIdx.x * 64;
    float S = g_sumexp;
    {
        int i = base + tid;
        if (i < n) { w[tid] = expf(__ldg(&x[i * 6 + 4])) / S; bb[tid] = load_idx(batch, i); }
        else { w[tid] = 0.f; bb[tid] = -1; }
    }
    __syncthreads();
    int m = n - base; if (m > 64) m = 64;
    if (m == 64 && bb[0] == bb[63]) {
        float a0 = 0.f, a1 = 0.f, a2 = 0.f, a3 = 0.f;
        for (int j = 0; j < 64; j += 4) {
            float h0 = __ldg(&g_h[(base + j + 0) * 64 + tid]);
            float h1 = __ldg(&g_h[(base + j + 1) * 64 + tid]);
            float h2 = __ldg(&g_h[(base + j + 2) * 64 + tid]);
            float h3 = __ldg(&g_h[(base + j + 3) * 64 + tid]);
            a0 += w[j] * h0; a1 += w[j + 1] * h1; a2 += w[j + 2] * h2; a3 += w[j + 3] * h3;
        }
        atomicAdd(&g_pool[bb[0] * 64 + tid], (a0 + a1) + (a2 + a3));
    } else {
        float acc = 0.f;
        int cur = bb[0];
        for (int j = 0; j < m; j++) {
            int b = bb[j];
            if (b != cur) {
                if (cur >= 0) atomicAdd(&g_pool[cur * 64 + tid], acc);
                acc = 0.f; cur = b;
            }
            acc += w[j] * __ldg(&g_h[(base + j) * 64 + tid]);
        }
        if (cur >= 0 && m > 0) atomicAdd(&g_pool[cur * 64 + tid], acc);
    }
}

// ---------------- heads ----------------
__global__ void k_head(const float* __restrict__ phW1, const float* __restrict__ phb1,
                       const float* __restrict__ phW2, const float* __restrict__ phb2,
                       const float* __restrict__ trW1, const float* __restrict__ trb1,
                       const float* __restrict__ trW2, const float* __restrict__ trb2,
                       float* __restrict__ out) {
    __shared__ float pool[64 * 64];
    __shared__ float hid[64 * 32];
    __shared__ float hidt[64 * 16];
    int tid = threadIdx.x;
    for (int i = tid; i < 64 * 64; i += 256) {
        int b = i >> 6;
        float c = (float)g_bcnt[b];
        pool[i] = g_pool[i] / fmaxf(c, 1.f);
    }
    __syncthreads();
    for (int i = tid; i < 64 * 32; i += 256) {
        int b = i >> 5, j = i & 31;
        float s = phb1[j];
        for (int k = 0; k < 64; k++) s += pool[b * 64 + k] * phW1[k * 32 + j];
        hid[i] = fmaxf(s, 0.f);
    }
    for (int i = tid; i < 64 * 16; i += 256) {
        int b = i >> 4, j = i & 15;
        float s = trb1[j];
        for (int k = 0; k < 64; k++) s += pool[b * 64 + k] * trW1[k * 16 + j];
        hidt[i] = fmaxf(s, 0.f);
    }
    __syncthreads();
    for (int i = tid; i < 64 * 3; i += 256) {
        int b = i / 3, j = i - b * 3;
        float s = phb2[j];
        for (int k = 0; k < 32; k++) s += hid[b * 32 + k] * phW2[k * 3 + j];
        out[i] = s;
    }
    for (int i = tid; i < 64; i += 256) {
        float s = trb2[0];
        for (int k = 0; k < 16; k++) s += hidt[i * 16 + k] * trW2[k];
        out[192 + i] = 1.f / (1.f + expf(-s));
    }
}

// ---------------- launch ----------------
extern "C" void kernel_launch(void* const* d_in, const int* in_sizes, int n_in,
                              void* d_out, int out_size) {
    const float* x   = (const float*)d_in[0];
    const void*  ei  = d_in[1];
    const void*  bat = d_in[2];
    const float* W1l = (const float*)d_in[3];
    const float* b1  = (const float*)d_in[4];
    const float* W1r = (const float*)d_in[5];
    const float* W2l = (const float*)d_in[6];
    const float* b2  = (const float*)d_in[7];
    const float* W2r = (const float*)d_in[8];
    const float* W3l = (const float*)d_in[9];
    const float* b3  = (const float*)d_in[10];
    const float* W3r = (const float*)d_in[11];
    const float* g1  = (const float*)d_in[12];
    const float* be1 = (const float*)d_in[13];
    const float* g2  = (const float*)d_in[14];
    const float* be2 = (const float*)d_in[15];
    const float* g3  = (const float*)d_in[16];
    const float* be3 = (const float*)d_in[17];
    const float* phW1 = (const float*)d_in[18];
    const float* phb1 = (const float*)d_in[19];
    const float* phW2 = (const float*)d_in[20];
    const float* phb2 = (const float*)d_in[21];
    const float* trW1 = (const float*)d_in[22];
    const float* trb1 = (const float*)d_in[23];
    const float* trW2 = (const float*)d_in[24];
    const float* trb2 = (const float*)d_in[25];
    float* out = (float*)d_out;

    int n = in_sizes[0] / 6;
    int e = in_sizes[1] / 2;

    float *p_agg, *p_agg6, *p_h, *p_stats;
    cudaGetSymbolAddress((void**)&p_agg, g_agg);
    cudaGetSymbolAddress((void**)&p_agg6, g_agg6);
    cudaGetSymbolAddress((void**)&p_h, g_h);
    cudaGetSymbolAddress((void**)&p_stats, g_stats);

    // detect + init + CSR
    k_detect<<<1, 32>>>((const long long*)ei, n);
    k_zero<<<(n + 255) / 256, 256>>>(n);
    k_hist<<<(e + 255) / 256, 256>>>(ei, e);
    int nb = (n + 1023) / 1024;
    k_scan1<<<nb, 1024>>>(n);
    k_scan2<<<1, 1024>>>(nb, n, e);
    k_scan3<<<nb, 1024>>>(n);
    k_scatter<<<(e + 255) / 256, 256>>>(ei, e);

    int aggBlocks = (n * 32 + 255) / 256;
    int mmBlocks = (n + 63) / 64;
    int bnBlocks = (n * 16 + 255) / 256;
    int nodeBlocks = (n + 63) / 64;

    // layer 1
    k_agg6<<<aggBlocks, 256>>>(x, n);
    k_mm<6, 8, 6><<<mmBlocks, 256>>>(p_agg6, x, W1l, W1r, b1, p_stats + 0 * 128, n);
    k_bnfin<<<1, 64>>>(p_stats + 0 * 128, g1, be1, 1.f / (float)n);
    k_bnapply<<<bnBlocks, 256>>>(n);

    // layer 2
    k_agg64<<<aggBlocks, 256>>>(p_h, n);
    k_mm<64, 64, 64><<<mmBlocks, 256>>>(p_agg, p_h, W2l, W2r, b2, p_stats + 1 * 128, n);
    k_bnfin<<<1, 64>>>(p_stats + 1 * 128, g2, be2, 1.f / (float)n);
    k_bnapply<<<bnBlocks, 256>>>(n);

    // layer 3
    k_agg64<<<aggBlocks, 256>>>(p_h, n);
    k_mm<64, 64, 64><<<mmBlocks, 256>>>(p_agg, p_h, W3l, W3r, b3, p_stats + 2 * 128, n);
    k_bnfin<<<1, 64>>>(p_stats + 2 * 128, g3, be3, 1.f / (float)n);
    k_bnapply<<<bnBlocks, 256>>>(n);

    // pooling + heads
    k_prepool<<<(n + 255) / 256, 256>>>(x, bat, n);
    k_pool<<<nodeBlocks, 64>>>(bat, x, n);
    k_head<<<1, 256>>>(phW1, phb1, phW2, phb2, trW1, trb1, trW2, trb2, out);
}

// round 4
// speedup vs baseline: 1.7896x; 1.0432x over previous
#include <cuda_runtime.h>

#define MAXN 100000
#define MAXE 1600000
#define HIDC 64
#define NB 64

// ---------------- device scratch ----------------
__device__ __align__(16) int   g_deg[MAXN];
__device__ __align__(16) int   g_off[MAXN + 1];
__device__ __align__(16) int   g_cur[MAXN];
__device__ __align__(16) int   g_srcidx[MAXE];
__device__ __align__(16) int   g_part[1024];
__device__ __align__(16) float g_h[MAXN * HIDC];
__device__ __align__(16) float g_y[MAXN * HIDC];
__device__ __align__(16) float g_agg[MAXN * HIDC];
__device__ __align__(16) float g_agg6[MAXN * 8];
__device__ __align__(16) float g_stats[3 * 2 * HIDC];
__device__ float g_sumexp;
__device__ __align__(16) float g_pool[NB * HIDC];
__device__ int   g_bcnt[NB];
__device__ int   g_is64;

// ---------------- f32x2 packed math helpers ----------------
__device__ __forceinline__ unsigned long long pack2(float lo, float hi) {
    unsigned long long r;
    asm("mov.b64 %0, {%1, %2};" : "=l"(r) : "f"(lo), "f"(hi));
    return r;
}
__device__ __forceinline__ void fma2(unsigned long long& d, unsigned long long a, unsigned long long b) {
    asm("fma.rn.f32x2 %0, %1, %2, %0;" : "+l"(d) : "l"(a), "l"(b));
}
__device__ __forceinline__ float2 unpack2(unsigned long long v) {
    float lo, hi;
    asm("mov.b64 {%0, %1}, %2;" : "=f"(lo), "=f"(hi) : "l"(v));
    return make_float2(lo, hi);
}

// ---------------- dtype detection (parallel) ----------------
__global__ void k_detect(const long long* __restrict__ ei, int n) {
    int lane = threadIdx.x;
    int bad = 0;
    for (int i = lane; i < 512; i += 32) {
        long long v = ei[i];
        bad |= (v < 0 || v >= (long long)n) ? 1 : 0;
    }
    bad = __any_sync(0xffffffffu, bad);
    if (lane == 0) g_is64 = bad ? 0 : 1;
}

__device__ __forceinline__ int load_idx(const void* p, int i) {
    if (g_is64) return (int)((const long long*)p)[i];
    return ((const int*)p)[i];
}

// ---------------- init ----------------
__global__ void k_zero(int n) {
    int i = blockIdx.x * blockDim.x + threadIdx.x;
    if (i < n) g_deg[i] = 0;
    if (i < 3 * 2 * HIDC) g_stats[i] = 0.f;
    if (i < NB * HIDC) g_pool[i] = 0.f;
    if (i < NB) g_bcnt[i] = 0;
    if (i == 0) g_sumexp = 0.f;
}

// ---------------- CSR build ----------------
__global__ void k_hist(const void* __restrict__ ei, int e) {
    int i = blockIdx.x * blockDim.x + threadIdx.x;
    if (i >= e) return;
    atomicAdd(&g_deg[load_idx(ei, e + i)], 1);
}

__global__ void k_scan1(int n) {
    __shared__ int sh[1024];
    int t = threadIdx.x;
    int i = blockIdx.x * 1024 + t;
    int v = (i < n) ? g_deg[i] : 0;
    sh[t] = v; __syncthreads();
    for (int d = 512; d > 0; d >>= 1) {
        if (t < d) sh[t] += sh[t + d];
        __syncthreads();
    }
    if (t == 0) g_part[blockIdx.x] = sh[0];
}

__global__ void k_scan2(int nb, int n, int e) {
    __shared__ int sh[1024];
    int t = threadIdx.x;
    int v = (t < nb) ? g_part[t] : 0;
    sh[t] = v; __syncthreads();
    for (int d = 1; d < 1024; d <<= 1) {
        int add = (t >= d) ? sh[t - d] : 0;
        __syncthreads();
        sh[t] += add;
        __syncthreads();
    }
    if (t < nb) g_part[t] = sh[t] - v;
    if (t == 0) g_off[n] = e;
}

__global__ void k_scan3(int n) {
    __shared__ int sh[1024];
    int t = threadIdx.x;
    int i = blockIdx.x * 1024 + t;
    int v = (i < n) ? g_deg[i] : 0;
    sh[t] = v; __syncthreads();
    for (int d = 1; d < 1024; d <<= 1) {
        int add = (t >= d) ? sh[t - d] : 0;
        __syncthreads();
        sh[t] += add;
        __syncthreads();
    }
    int excl = sh[t] - v + g_part[blockIdx.x];
    if (i < n) { g_off[i] = excl; g_cur[i] = excl; }
}

__global__ void k_scatter(const void* __restrict__ ei, int e) {
    int i = blockIdx.x * blockDim.x + threadIdx.x;
    if (i >= e) return;
    int src = load_idx(ei, i);
    int dst = load_idx(ei, e + i);
    int pos = atomicAdd(&g_cur[dst], 1);
    g_srcidx[pos] = src;
}

// ---------------- aggregation ----------------
__global__ void k_agg6(const float* __restrict__ x, int n) {
    int w = (blockIdx.x * blockDim.x + threadIdx.x) >> 5;
    int lane = threadIdx.x & 31;
    if (w >= n) return;
    int s = g_off[w], t = g_off[w + 1];
    float acc = 0.f;
    int e = s;
    for (; e + 4 <= t; e += 4) {
        int i0 = __ldg(&g_srcidx[e]);
        int i1 = __ldg(&g_srcidx[e + 1]);
        int i2 = __ldg(&g_srcidx[e + 2]);
        int i3 = __ldg(&g_srcidx[e + 3]);
        if (lane < 6) {
            float a0 = __ldg(&x[i0 * 6 + lane]);
            float a1 = __ldg(&x[i1 * 6 + lane]);
            float a2 = __ldg(&x[i2 * 6 + lane]);
            float a3 = __ldg(&x[i3 * 6 + lane]);
            acc += (a0 + a1) + (a2 + a3);
        }
    }
    for (; e < t; e++) {
        int i0 = __ldg(&g_srcidx[e]);
        if (lane < 6) acc += __ldg(&x[i0 * 6 + lane]);
    }
    float inv = 1.f / fmaxf((float)(t - s), 1.f);
    if (lane < 8) g_agg6[w * 8 + lane] = (lane < 6) ? acc * inv : 0.f;
}

// 64-channel gather, one warp per node, lane = 2 channels, MLP=8
__global__ void k_agg64(const float* __restrict__ hin, int n) {
    int w = (blockIdx.x * blockDim.x + threadIdx.x) >> 5;
    int lane = threadIdx.x & 31;
    if (w >= n) return;
    int s = g_off[w], t = g_off[w + 1];
    float ax = 0.f, ay = 0.f;
    const float2* hp = (const float2*)hin;
    int e = s;
    for (; e + 8 <= t; e += 8) {
        int i0 = __ldg(&g_srcidx[e]);
        int i1 = __ldg(&g_srcidx[e + 1]);
        int i2 = __ldg(&g_srcidx[e + 2]);
        int i3 = __ldg(&g_srcidx[e + 3]);
        int i4 = __ldg(&g_srcidx[e + 4]);
        int i5 = __ldg(&g_srcidx[e + 5]);
        int i6 = __ldg(&g_srcidx[e + 6]);
        int i7 = __ldg(&g_srcidx[e + 7]);
        float2 v0 = __ldg(&hp[i0 * 32 + lane]);
        float2 v1 = __ldg(&hp[i1 * 32 + lane]);
        float2 v2 = __ldg(&hp[i2 * 32 + lane]);
        float2 v3 = __ldg(&hp[i3 * 32 + lane]);
        float2 v4 = __ldg(&hp[i4 * 32 + lane]);
        float2 v5 = __ldg(&hp[i5 * 32 + lane]);
        float2 v6 = __ldg(&hp[i6 * 32 + lane]);
        float2 v7 = __ldg(&hp[i7 * 32 + lane]);
        ax += ((v0.x + v1.x) + (v2.x + v3.x)) + ((v4.x + v5.x) + (v6.x + v7.x));
        ay += ((v0.y + v1.y) + (v2.y + v3.y)) + ((v4.y + v5.y) + (v6.y + v7.y));
    }
    for (; e < t; e++) {
        int i0 = __ldg(&g_srcidx[e]);
        float2 v = __ldg(&hp[i0 * 32 + lane]);
        ax += v.x; ay += v.y;
    }
    float inv = 1.f / fmaxf((float)(t - s), 1.f);
    float2 o; o.x = ax * inv; o.y = ay * inv;
    ((float2*)g_agg)[w * 32 + lane] = o;
}

// ---------------- dense matmul (FFMA2) + BN-stats ----------------
// Weights staged in smem pair-interleaved: (k,c) -> ((k>>1)*64 + c)*2 + (k&1),
// so one float4 = w[k..k+1][c..c+1]; activations (a.x,a.y) are aligned f32x2 pairs.
template <int DIN, int SA, int SH>
__global__ void __launch_bounds__(256)
k_mm(const float* __restrict__ aggin, const float* __restrict__ hin,
     const float* __restrict__ Wl, const float* __restrict__ Wr,
     const float* __restrict__ bias, float* __restrict__ stats, int n) {
    __shared__ float sWl[DIN * 64];
    __shared__ float sWr[DIN * 64];
    __shared__ float sb[64];
    __shared__ float redS[8][64];
    __shared__ float redQ[8][64];
    int tid = threadIdx.x;
    if (DIN == 64) {
        for (int i = tid; i < DIN * 64; i += 256) {
            int k = i >> 6, c = i & 63;
            int dst = (((k >> 1) << 6) + c) * 2 + (k & 1);
            sWl[dst] = Wl[i]; sWr[dst] = Wr[i];
        }
    } else {
        for (int i = tid; i < DIN * 64; i += 256) { sWl[i] = Wl[i]; sWr[i] = Wr[i]; }
    }
    if (tid < 64) sb[tid] = bias[tid];
    __syncthreads();

    int warp = tid >> 5, lane = tid & 31;
    int c0 = lane * 2;
    int base = (blockIdx.x * 8 + warp) * 8;

    float y[8][2];

    if (DIN == 64) {
        unsigned long long acc0[8], acc1[8];
#pragma unroll
        for (int j = 0; j < 8; j++) {
            acc0[j] = pack2(sb[c0], 0.f);
            acc1[j] = pack2(sb[c0 + 1], 0.f);
        }
#pragma unroll 4
        for (int k = 0; k < 64; k += 4) {
            // float4 = (w[k][c0], w[k+1][c0], w[k][c0+1], w[k+1][c0+1])
            float4 wl01 = *(float4*)&sWl[((k >> 1) * 64 + c0) * 2];
            float4 wl23 = *(float4*)&sWl[(((k >> 1) + 1) * 64 + c0) * 2];
            float4 wr01 = *(float4*)&sWr[((k >> 1) * 64 + c0) * 2];
            float4 wr23 = *(float4*)&sWr[(((k >> 1) + 1) * 64 + c0) * 2];
            unsigned long long pl0a = pack2(wl01.x, wl01.y);
            unsigned long long pl0b = pack2(wl01.z, wl01.w);
            unsigned long long pl1a = pack2(wl23.x, wl23.y);
            unsigned long long pl1b = pack2(wl23.z, wl23.w);
            unsigned long long pr0a = pack2(wr01.x, wr01.y);
            unsigned long long pr0b = pack2(wr01.z, wr01.w);
            unsigned long long pr1a = pack2(wr23.x, wr23.y);
            unsigned long long pr1b = pack2(wr23.z, wr23.w);
#pragma unroll
            for (int j = 0; j < 8; j++) {
                int node = base + j; if (node >= n) node = n - 1;
                float4 a = *(const float4*)&aggin[node * SA + k];
                float4 h = *(const float4*)&hin[node * SH + k];
                unsigned long long axy = pack2(a.x, a.y);
                unsigned long long azw = pack2(a.z, a.w);
                unsigned long long hxy = pack2(h.x, h.y);
                unsigned long long hzw = pack2(h.z, h.w);
                fma2(acc0[j], axy, pl0a);
                fma2(acc1[j], axy, pl0b);
                fma2(acc0[j], azw, pl1a);
                fma2(acc1[j], azw, pl1b);
                fma2(acc0[j], hxy, pr0a);
                fma2(acc1[j], hxy, pr0b);
                fma2(acc0[j], hzw, pr1a);
                fma2(acc1[j], hzw, pr1b);
            }
        }
#pragma unroll
        for (int j = 0; j < 8; j++) {
            float2 u0 = unpack2(acc0[j]);
            float2 u1 = unpack2(acc1[j]);
            y[j][0] = u0.x + u0.y;
            y[j][1] = u1.x + u1.y;
        }
    } else {
#pragma unroll
        for (int j = 0; j < 8; j++) { y[j][0] = sb[c0]; y[j][1] = sb[c0 + 1]; }
#pragma unroll
        for (int k = 0; k < DIN; k++) {
            float2 wl = *(float2*)&sWl[k * 64 + c0];
            float2 wr = *(float2*)&sWr[k * 64 + c0];
#pragma unroll
            for (int j = 0; j < 8; j++) {
                int node = base + j; if (node >= n) node = n - 1;
                float a = __ldg(&aggin[node * SA + k]);
                float h = __ldg(&hin[node * SH + k]);
                y[j][0] += a * wl.x + h * wr.x;
                y[j][1] += a * wl.y + h * wr.y;
            }
        }
    }

    float ls0 = 0.f, ls1 = 0.f, lq0 = 0.f, lq1 = 0.f;
#pragma unroll
    for (int j = 0; j < 8; j++) {
        int node = base + j;
        if (node < n) {
            float v0 = y[j][0], v1 = y[j][1];
            float2 o; o.x = v0; o.y = v1;
            *(float2*)&g_y[node * 64 + c0] = o;
            ls0 += v0; lq0 += v0 * v0;
            ls1 += v1; lq1 += v1 * v1;
        }
    }
    redS[warp][c0] = ls0; redS[warp][c0 + 1] = ls1;
    redQ[warp][c0] = lq0; redQ[warp][c0 + 1] = lq1;
    __syncthreads();
    if (tid < 64) {
        float s = 0.f, q = 0.f;
#pragma unroll
        for (int w2 = 0; w2 < 8; w2++) { s += redS[w2][tid]; q += redQ[w2][tid]; }
        atomicAdd(&stats[tid], s);
        atomicAdd(&stats[64 + tid], q);
    }
}

// ---------------- BN finalize+apply (fused; per-block scale/shift recompute) ----------------
__global__ void k_bnapply(const float* __restrict__ stats,
                          const float* __restrict__ g, const float* __restrict__ be,
                          float invn, int n) {
    __shared__ float ssc[64], ssh[64];
    int tid = threadIdx.x;
    if (tid < 64) {
        float mu = stats[tid] * invn;
        float var = stats[64 + tid] * invn - mu * mu;
        float rstd = rsqrtf(var + 1e-5f);
        float sc = rstd * g[tid];
        ssc[tid] = sc;
        ssh[tid] = be[tid] - mu * sc;
    }
    __syncthreads();
    int i = blockIdx.x * blockDim.x + tid;  // over n*16 float4s
    if (i >= n * 16) return;
    float4 v = *(const float4*)&g_y[i * 4];
    int c = (i & 15) * 4;
    v.x = fmaxf(fmaf(v.x, ssc[c],     ssh[c]),     0.f);
    v.y = fmaxf(fmaf(v.y, ssc[c + 1], ssh[c + 1]), 0.f);
    v.z = fmaxf(fmaf(v.z, ssc[c + 2], ssh[c + 2]), 0.f);
    v.w = fmaxf(fmaf(v.w, ssc[c + 3], ssh[c + 3]), 0.f);
    *(float4*)&g_h[i * 4] = v;
}

// ---------------- pooling ----------------
__global__ void k_prepool(const float* __restrict__ x, const void* __restrict__ batch, int n) {
    __shared__ float ssum[256];
    __shared__ int hist[64];
    int tid = threadIdx.x;
    if (tid < 64) hist[tid] = 0;
    __syncthreads();
    int i = blockIdx.x * blockDim.x + tid;
    float loc = 0.f;
    if (i < n) {
        loc = expf(__ldg(&x[i * 6 + 4]));
        atomicAdd(&hist[load_idx(batch, i)], 1);
    }
    ssum[tid] = loc; __syncthreads();
    for (int d = 128; d > 0; d >>= 1) {
        if (tid < d) ssum[tid] += ssum[tid + d];
        __syncthreads();
    }
    if (tid == 0) atomicAdd(&g_sumexp, ssum[0]);
    if (tid < 64 && hist[tid]) atomicAdd(&g_bcnt[tid], hist[tid]);
}

__global__ void k_pool(const void* __restrict__ batch, const float* __restrict__ x, int n) {
    __shared__ float w[64];
    __shared__ int bb[64];
    int tid = threadIdx.x;
    int base = blockIdx.x * 64;
    float S = g_sumexp;
    {
        int i = base + tid;
        if (i < n) { w[tid] = expf(__ldg(&x[i * 6 + 4])) / S; bb[tid] = load_idx(batch, i); }
        else { w[tid] = 0.f; bb[tid] = -1; }
    }
    __syncthreads();
    int m = n - base; if (m > 64) m = 64;
    if (m == 64 && bb[0] == bb[63]) {
        float a0 = 0.f, a1 = 0.f, a2 = 0.f, a3 = 0.f;
        for (int j = 0; j < 64; j += 4) {
            float h0 = __ldg(&g_h[(base + j + 0) * 64 + tid]);
            float h1 = __ldg(&g_h[(base + j + 1) * 64 + tid]);
            float h2 = __ldg(&g_h[(base + j + 2) * 64 + tid]);
            float h3 = __ldg(&g_h[(base + j + 3) * 64 + tid]);
            a0 += w[j] * h0; a1 += w[j + 1] * h1; a2 += w[j + 2] * h2; a3 += w[j + 3] * h3;
        }
        atomicAdd(&g_pool[bb[0] * 64 + tid], (a0 + a1) + (a2 + a3));
    } else {
        float acc = 0.f;
        int cur = bb[0];
        for (int j = 0; j < m; j++) {
            int b = bb[j];
            if (b != cur) {
                if (cur >= 0) atomicAdd(&g_pool[cur * 64 + tid], acc);
                acc = 0.f; cur = b;
            }
            acc += w[j] * __ldg(&g_h[(base + j) * 64 + tid]);
        }
        if (cur >= 0 && m > 0) atomicAdd(&g_pool[cur * 64 + tid], acc);
    }
}

// ---------------- heads ----------------
__global__ void k_head(const float* __restrict__ phW1, const float* __restrict__ phb1,
                       const float* __restrict__ phW2, const float* __restrict__ phb2,
                       const float* __restrict__ trW1, const float* __restrict__ trb1,
                       const float* __restrict__ trW2, const float* __restrict__ trb2,
                       float* __restrict__ out) {
    __shared__ float pool[64 * 64];
    __shared__ float hid[64 * 32];
    __shared__ float hidt[64 * 16];
    int tid = threadIdx.x;
    for (int i = tid; i < 64 * 64; i += 256) {
        int b = i >> 6;
        float c = (float)g_bcnt[b];
        pool[i] = g_pool[i] / fmaxf(c, 1.f);
    }
    __syncthreads();
    for (int i = tid; i < 64 * 32; i += 256) {
        int b = i >> 5, j = i & 31;
        float s = phb1[j];
        for (int k = 0; k < 64; k++) s += pool[b * 64 + k] * phW1[k * 32 + j];
        hid[i] = fmaxf(s, 0.f);
    }
    for (int i = tid; i < 64 * 16; i += 256) {
        int b = i >> 4, j = i & 15;
        float s = trb1[j];
        for (int k = 0; k < 64; k++) s += pool[b * 64 + k] * trW1[k * 16 + j];
        hidt[i] = fmaxf(s, 0.f);
    }
    __syncthreads();
    for (int i = tid; i < 64 * 3; i += 256) {
        int b = i / 3, j = i - b * 3;
        float s = phb2[j];
        for (int k = 0; k < 32; k++) s += hid[b * 32 + k] * phW2[k * 3 + j];
        out[i] = s;
    }
    for (int i = tid; i < 64; i += 256) {
        float s = trb2[0];
        for (int k = 0; k < 16; k++) s += hidt[i * 16 + k] * trW2[k];
        out[192 + i] = 1.f / (1.f + expf(-s));
    }
}

// ---------------- launch ----------------
extern "C" void kernel_launch(void* const* d_in, const int* in_sizes, int n_in,
                              void* d_out, int out_size) {
    const float* x   = (const float*)d_in[0];
    const void*  ei  = d_in[1];
    const void*  bat = d_in[2];
    const float* W1l = (const float*)d_in[3];
    const float* b1  = (const float*)d_in[4];
    const float* W1r = (const float*)d_in[5];
    const float* W2l = (const float*)d_in[6];
    const float* b2  = (const float*)d_in[7];
    const float* W2r = (const float*)d_in[8];
    const float* W3l = (const float*)d_in[9];
    const float* b3  = (const float*)d_in[10];
    const float* W3r = (const float*)d_in[11];
    const float* g1  = (const float*)d_in[12];
    const float* be1 = (const float*)d_in[13];
    const float* g2  = (const float*)d_in[14];
    const float* be2 = (const float*)d_in[15];
    const float* g3  = (const float*)d_in[16];
    const float* be3 = (const float*)d_in[17];
    const float* phW1 = (const float*)d_in[18];
    const float* phb1 = (const float*)d_in[19];
    const float* phW2 = (const float*)d_in[20];
    const float* phb2 = (const float*)d_in[21];
    const float* trW1 = (const float*)d_in[22];
    const float* trb1 = (const float*)d_in[23];
    const float* trW2 = (const float*)d_in[24];
    const float* trb2 = (const float*)d_in[25];
    float* out = (float*)d_out;

    int n = in_sizes[0] / 6;
    int e = in_sizes[1] / 2;

    float *p_agg, *p_agg6, *p_h, *p_stats;
    cudaGetSymbolAddress((void**)&p_agg, g_agg);
    cudaGetSymbolAddress((void**)&p_agg6, g_agg6);
    cudaGetSymbolAddress((void**)&p_h, g_h);
    cudaGetSymbolAddress((void**)&p_stats, g_stats);

    // detect + init + CSR
    k_detect<<<1, 32>>>((const long long*)ei, n);
    k_zero<<<(n + 255) / 256, 256>>>(n);
    k_hist<<<(e + 255) / 256, 256>>>(ei, e);
    int nb = (n + 1023) / 1024;
    k_scan1<<<nb, 1024>>>(n);
    k_scan2<<<1, 1024>>>(nb, n, e);
    k_scan3<<<nb, 1024>>>(n);
    k_scatter<<<(e + 255) / 256, 256>>>(ei, e);

    int aggBlocks = (n * 32 + 255) / 256;
    int mmBlocks = (n + 63) / 64;
    int bnBlocks = (n * 16 + 255) / 256;
    int nodeBlocks = (n + 63) / 64;
    float invn = 1.f / (float)n;

    // layer 1
    k_agg6<<<aggBlocks, 256>>>(x, n);
    k_mm<6, 8, 6><<<mmBlocks, 256>>>(p_agg6, x, W1l, W1r, b1, p_stats + 0 * 128, n);
    k_bnapply<<<bnBlocks, 256>>>(p_stats + 0 * 128, g1, be1, invn, n);

    // layer 2
    k_agg64<<<aggBlocks, 256>>>(p_h, n);
    k_mm<64, 64, 64><<<mmBlocks, 256>>>(p_agg, p_h, W2l, W2r, b2, p_stats + 1 * 128, n);
    k_bnapply<<<bnBlocks, 256>>>(p_stats + 1 * 128, g2, be2, invn, n);

    // layer 3
    k_agg64<<<aggBlocks, 256>>>(p_h, n);
    k_mm<64, 64, 64><<<mmBlocks, 256>>>(p_agg, p_h, W3l, W3r, b3, p_stats + 2 * 128, n);
    k_bnapply<<<bnBlocks, 256>>>(p_stats + 2 * 128, g3, be3, invn, n);

    // pooling + heads
    k_prepool<<<(n + 255) / 256, 256>>>(x, bat, n);
    k_pool<<<nodeBlocks, 64>>>(bat, x, n);
    k_head<<<1, 256>>>(phW1, phb1, phW2, phb2, trW1, trb1, trW2, trb2, out);
}

// round 5
// speedup vs baseline: 1.8165x; 1.0150x over previous
#include <cuda_runtime.h>
#include <cuda_fp16.h>

#define MAXN 100000
#define MAXE 1600000
#define HIDC 64
#define NB 64

// ---------------- device scratch ----------------
__device__ __align__(16) int    g_deg[MAXN];
__device__ __align__(16) int    g_off[MAXN + 1];
__device__ __align__(16) int    g_cur[MAXN];
__device__ __align__(16) int    g_srcidx[MAXE];
__device__ __align__(16) int    g_part[1024];
__device__ __align__(16) __half2 g_y16a[MAXN * 32];   // layer1 / layer3 output (fp16)
__device__ __align__(16) __half2 g_y16b[MAXN * 32];   // layer2 output (fp16)
__device__ __align__(16) float  g_agg[MAXN * HIDC];   // fp32 aggregate (mm input)
__device__ __align__(16) float  g_hself[MAXN * HIDC]; // fp32 BN'd self features (mm input)
__device__ __align__(16) float  g_agg6[MAXN * 8];
__device__ __align__(16) float  g_stats[3 * 2 * HIDC];
__device__ float g_sumexp;
__device__ __align__(16) float  g_pool[NB * HIDC];
__device__ int   g_bcnt[NB];
__device__ int   g_is64;

// ---------------- f32x2 packed math helpers ----------------
__device__ __forceinline__ unsigned long long pack2(float lo, float hi) {
    unsigned long long r;
    asm("mov.b64 %0, {%1, %2};" : "=l"(r) : "f"(lo), "f"(hi));
    return r;
}
__device__ __forceinline__ void fma2(unsigned long long& d, unsigned long long a, unsigned long long b) {
    asm("fma.rn.f32x2 %0, %1, %2, %0;" : "+l"(d) : "l"(a), "l"(b));
}
__device__ __forceinline__ float2 unpack2(unsigned long long v) {
    float lo, hi;
    asm("mov.b64 {%0, %1}, %2;" : "=f"(lo), "=f"(hi) : "l"(v));
    return make_float2(lo, hi);
}

__device__ __forceinline__ int load_idx(const void* p, int i) {
    if (g_is64) return (int)((const long long*)p)[i];
    return ((const int*)p)[i];
}

// ---------------- init (zero + dtype detect fused) ----------------
__global__ void k_init(const long long* __restrict__ ei, int n) {
    int i = blockIdx.x * blockDim.x + threadIdx.x;
    if (blockIdx.x == 0 && threadIdx.x < 32) {
        int lane = threadIdx.x;
        int bad = 0;
        for (int k = lane; k < 512; k += 32) {
            long long v = ei[k];
            bad |= (v < 0 || v >= (long long)n) ? 1 : 0;
        }
        bad = __any_sync(0xffffffffu, bad);
        if (lane == 0) g_is64 = bad ? 0 : 1;
    }
    if (i < n) g_deg[i] = 0;
    if (i < 3 * 2 * HIDC) g_stats[i] = 0.f;
    if (i < NB * HIDC) g_pool[i] = 0.f;
    if (i < NB) g_bcnt[i] = 0;
    if (i == 0) g_sumexp = 0.f;
}

// ---------------- CSR build ----------------
__global__ void k_hist(const void* __restrict__ ei, int e) {
    int i = blockIdx.x * blockDim.x + threadIdx.x;
    if (i >= e) return;
    atomicAdd(&g_deg[load_idx(ei, e + i)], 1);
}

__global__ void k_scan1(int n) {
    __shared__ int sh[1024];
    int t = threadIdx.x;
    int i = blockIdx.x * 1024 + t;
    int v = (i < n) ? g_deg[i] : 0;
    sh[t] = v; __syncthreads();
    for (int d = 512; d > 0; d >>= 1) {
        if (t < d) sh[t] += sh[t + d];
        __syncthreads();
    }
    if (t == 0) g_part[blockIdx.x] = sh[0];
}

__global__ void k_scan2(int nb, int n, int e) {
    __shared__ int sh[1024];
    int t = threadIdx.x;
    int v = (t < nb) ? g_part[t] : 0;
    sh[t] = v; __syncthreads();
    for (int d = 1; d < 1024; d <<= 1) {
        int add = (t >= d) ? sh[t - d] : 0;
        __syncthreads();
        sh[t] += add;
        __syncthreads();
    }
    if (t < nb) g_part[t] = sh[t] - v;
    if (t == 0) g_off[n] = e;
}

__global__ void k_scan3(int n) {
    __shared__ int sh[1024];
    int t = threadIdx.x;
    int i = blockIdx.x * 1024 + t;
    int v = (i < n) ? g_deg[i] : 0;
    sh[t] = v; __syncthreads();
    for (int d = 1; d < 1024; d <<= 1) {
        int add = (t >= d) ? sh[t - d] : 0;
        __syncthreads();
        sh[t] += add;
        __syncthreads();
    }
    int excl = sh[t] - v + g_part[blockIdx.x];
    if (i < n) { g_off[i] = excl; g_cur[i] = excl; }
}

__global__ void k_scatter(const void* __restrict__ ei, int e) {
    int i = blockIdx.x * blockDim.x + threadIdx.x;
    if (i >= e) return;
    int src = load_idx(ei, i);
    int dst = load_idx(ei, e + i);
    int pos = atomicAdd(&g_cur[dst], 1);
    g_srcidx[pos] = src;
}

// ---------------- layer-1 aggregation (x fp32, 6ch) ----------------
__global__ void k_agg6(const float* __restrict__ x, int n) {
    int w = (blockIdx.x * blockDim.x + threadIdx.x) >> 5;
    int lane = threadIdx.x & 31;
    if (w >= n) return;
    int s = g_off[w], t = g_off[w + 1];
    float acc = 0.f;
    int e = s;
    for (; e + 4 <= t; e += 4) {
        int i0 = __ldg(&g_srcidx[e]);
        int i1 = __ldg(&g_srcidx[e + 1]);
        int i2 = __ldg(&g_srcidx[e + 2]);
        int i3 = __ldg(&g_srcidx[e + 3]);
        if (lane < 6) {
            float a0 = __ldg(&x[i0 * 6 + lane]);
            float a1 = __ldg(&x[i1 * 6 + lane]);
            float a2 = __ldg(&x[i2 * 6 + lane]);
            float a3 = __ldg(&x[i3 * 6 + lane]);
            acc += (a0 + a1) + (a2 + a3);
        }
    }
    for (; e < t; e++) {
        int i0 = __ldg(&g_srcidx[e]);
        if (lane < 6) acc += __ldg(&x[i0 * 6 + lane]);
    }
    float inv = 1.f / fmaxf((float)(t - s), 1.f);
    if (lane < 8) g_agg6[w * 8 + lane] = (lane < 6) ? acc * inv : 0.f;
}

// ---------------- layers 2/3 aggregation: fp16 gather + BN-on-read ----------------
// One warp per node; lane owns channels (2*lane, 2*lane+1) = one half2 per lane.
// 128 B per edge (single L2 line). Also produces BN'd self features (fp32).
__global__ void k_agg64h(const __half2* __restrict__ yin,
                         const float* __restrict__ stats,
                         const float* __restrict__ gam, const float* __restrict__ bet,
                         float invn,
                         float* __restrict__ aggout, float* __restrict__ hselfout, int n) {
    __shared__ float ssc[64], ssh[64];
    int tid = threadIdx.x;
    if (tid < 64) {
        float mu = stats[tid] * invn;
        float var = stats[64 + tid] * invn - mu * mu;
        float rstd = rsqrtf(var + 1e-5f);
        float sc = rstd * gam[tid];
        ssc[tid] = sc;
        ssh[tid] = bet[tid] - mu * sc;
    }
    __syncthreads();
    int w = (blockIdx.x * blockDim.x + tid) >> 5;
    int lane = tid & 31;
    if (w >= n) return;
    float sc0 = ssc[lane * 2], sc1 = ssc[lane * 2 + 1];
    float sh0 = ssh[lane * 2], sh1 = ssh[lane * 2 + 1];
    int s = g_off[w], t = g_off[w + 1];
    float ax = 0.f, ay = 0.f;
    int e = s;
#define BNX(f) fmaxf(fmaf((f).x, sc0, sh0), 0.f)
#define BNY(f) fmaxf(fmaf((f).y, sc1, sh1), 0.f)
    for (; e + 8 <= t; e += 8) {
        int i0 = __ldg(&g_srcidx[e]);
        int i1 = __ldg(&g_srcidx[e + 1]);
        int i2 = __ldg(&g_srcidx[e + 2]);
        int i3 = __ldg(&g_srcidx[e + 3]);
        int i4 = __ldg(&g_srcidx[e + 4]);
        int i5 = __ldg(&g_srcidx[e + 5]);
        int i6 = __ldg(&g_srcidx[e + 6]);
        int i7 = __ldg(&g_srcidx[e + 7]);
        float2 f0 = __half22float2(__ldg(&yin[i0 * 32 + lane]));
        float2 f1 = __half22float2(__ldg(&yin[i1 * 32 + lane]));
        float2 f2 = __half22float2(__ldg(&yin[i2 * 32 + lane]));
        float2 f3 = __half22float2(__ldg(&yin[i3 * 32 + lane]));
        float2 f4 = __half22float2(__ldg(&yin[i4 * 32 + lane]));
        float2 f5 = __half22float2(__ldg(&yin[i5 * 32 + lane]));
        float2 f6 = __half22float2(__ldg(&yin[i6 * 32 + lane]));
        float2 f7 = __half22float2(__ldg(&yin[i7 * 32 + lane]));
        ax += ((BNX(f0) + BNX(f1)) + (BNX(f2) + BNX(f3)))
            + ((BNX(f4) + BNX(f5)) + (BNX(f6) + BNX(f7)));
        ay += ((BNY(f0) + BNY(f1)) + (BNY(f2) + BNY(f3)))
            + ((BNY(f4) + BNY(f5)) + (BNY(f6) + BNY(f7)));
    }
    for (; e < t; e++) {
        int i0 = __ldg(&g_srcidx[e]);
        float2 f = __half22float2(__ldg(&yin[i0 * 32 + lane]));
        ax += BNX(f); ay += BNY(f);
    }
#undef BNX
#undef BNY
    float inv = 1.f / fmaxf((float)(t - s), 1.f);
    float2 o; o.x = ax * inv; o.y = ay * inv;
    ((float2*)aggout)[w * 32 + lane] = o;
    // BN'd self feature
    float2 fs = __half22float2(__ldg(&yin[w * 32 + lane]));
    float2 hs;
    hs.x = fmaxf(fmaf(fs.x, sc0, sh0), 0.f);
    hs.y = fmaxf(fmaf(fs.y, sc1, sh1), 0.f);
    ((float2*)hselfout)[w * 32 + lane] = hs;
}

// ---------------- dense matmul (FFMA2) + BN-stats, fp16 output ----------------
template <int DIN, int SA, int SH>
__global__ void __launch_bounds__(256)
k_mm(const float* __restrict__ aggin, const float* __restrict__ hin,
     const float* __restrict__ Wl, const float* __restrict__ Wr,
     const float* __restrict__ bias, __half2* __restrict__ yout,
     float* __restrict__ stats, int n) {
    __shared__ float sWl[DIN * 64];
    __shared__ float sWr[DIN * 64];
    __shared__ float sb[64];
    __shared__ float redS[8][64];
    __shared__ float redQ[8][64];
    int tid = threadIdx.x;
    if (DIN == 64) {
        for (int i = tid; i < DIN * 64; i += 256) {
            int k = i >> 6, c = i & 63;
            int dst = (((k >> 1) << 6) + c) * 2 + (k & 1);
            sWl[dst] = Wl[i]; sWr[dst] = Wr[i];
        }
    } else {
        for (int i = tid; i < DIN * 64; i += 256) { sWl[i] = Wl[i]; sWr[i] = Wr[i]; }
    }
    if (tid < 64) sb[tid] = bias[tid];
    __syncthreads();

    int warp = tid >> 5, lane = tid & 31;
    int c0 = lane * 2;
    int base = (blockIdx.x * 8 + warp) * 8;

    float y[8][2];

    if (DIN == 64) {
        unsigned long long acc0[8], acc1[8];
#pragma unroll
        for (int j = 0; j < 8; j++) {
            acc0[j] = pack2(sb[c0], 0.f);
            acc1[j] = pack2(sb[c0 + 1], 0.f);
        }
#pragma unroll 4
        for (int k = 0; k < 64; k += 4) {
            float4 wl01 = *(float4*)&sWl[((k >> 1) * 64 + c0) * 2];
            float4 wl23 = *(float4*)&sWl[(((k >> 1) + 1) * 64 + c0) * 2];
            float4 wr01 = *(float4*)&sWr[((k >> 1) * 64 + c0) * 2];
            float4 wr23 = *(float4*)&sWr[(((k >> 1) + 1) * 64 + c0) * 2];
            unsigned long long pl0a = pack2(wl01.x, wl01.y);
            unsigned long long pl0b = pack2(wl01.z, wl01.w);
            unsigned long long pl1a = pack2(wl23.x, wl23.y);
            unsigned long long pl1b = pack2(wl23.z, wl23.w);
            unsigned long long pr0a = pack2(wr01.x, wr01.y);
            unsigned long long pr0b = pack2(wr01.z, wr01.w);
            unsigned long long pr1a = pack2(wr23.x, wr23.y);
            unsigned long long pr1b = pack2(wr23.z, wr23.w);
#pragma unroll
            for (int j = 0; j < 8; j++) {
                int node = base + j; if (node >= n) node = n - 1;
                float4 a = *(const float4*)&aggin[node * SA + k];
                float4 h = *(const float4*)&hin[node * SH + k];
                unsigned long long axy = pack2(a.x, a.y);
                unsigned long long azw = pack2(a.z, a.w);
                unsigned long long hxy = pack2(h.x, h.y);
                unsigned long long hzw = pack2(h.z, h.w);
                fma2(acc0[j], axy, pl0a);
                fma2(acc1[j], axy, pl0b);
                fma2(acc0[j], azw, pl1a);
                fma2(acc1[j], azw, pl1b);
                fma2(acc0[j], hxy, pr0a);
                fma2(acc1[j], hxy, pr0b);
                fma2(acc0[j], hzw, pr1a);
                fma2(acc1[j], hzw, pr1b);
            }
        }
#pragma unroll
        for (int j = 0; j < 8; j++) {
            float2 u0 = unpack2(acc0[j]);
            float2 u1 = unpack2(acc1[j]);
            y[j][0] = u0.x + u0.y;
            y[j][1] = u1.x + u1.y;
        }
    } else {
#pragma unroll
        for (int j = 0; j < 8; j++) { y[j][0] = sb[c0]; y[j][1] = sb[c0 + 1]; }
#pragma unroll
        for (int k = 0; k < DIN; k++) {
            float2 wl = *(float2*)&sWl[k * 64 + c0];
            float2 wr = *(float2*)&sWr[k * 64 + c0];
#pragma unroll
            for (int j = 0; j < 8; j++) {
                int node = base + j; if (node >= n) node = n - 1;
                float a = __ldg(&aggin[node * SA + k]);
                float h = __ldg(&hin[node * SH + k]);
                y[j][0] += a * wl.x + h * wr.x;
                y[j][1] += a * wl.y + h * wr.y;
            }
        }
    }

    float ls0 = 0.f, ls1 = 0.f, lq0 = 0.f, lq1 = 0.f;
#pragma unroll
    for (int j = 0; j < 8; j++) {
        int node = base + j;
        if (node < n) {
            float v0 = y[j][0], v1 = y[j][1];
            yout[node * 32 + lane] = __float22half2_rn(make_float2(v0, v1));
            ls0 += v0; lq0 += v0 * v0;
            ls1 += v1; lq1 += v1 * v1;
        }
    }
    redS[warp][c0] = ls0; redS[warp][c0 + 1] = ls1;
    redQ[warp][c0] = lq0; redQ[warp][c0 + 1] = lq1;
    __syncthreads();
    if (tid < 64) {
        float s = 0.f, q = 0.f;
#pragma unroll
        for (int w2 = 0; w2 < 8; w2++) { s += redS[w2][tid]; q += redQ[w2][tid]; }
        atomicAdd(&stats[tid], s);
        atomicAdd(&stats[64 + tid], q);
    }
}

// ---------------- pooling ----------------
__global__ void k_prepool(const float* __restrict__ x, const void* __restrict__ batch, int n) {
    __shared__ float ssum[256];
    __shared__ int hist[64];
    int tid = threadIdx.x;
    if (tid < 64) hist[tid] = 0;
    __syncthreads();
    int i = blockIdx.x * blockDim.x + tid;
    float loc = 0.f;
    if (i < n) {
        loc = expf(__ldg(&x[i * 6 + 4]));
        atomicAdd(&hist[load_idx(batch, i)], 1);
    }
    ssum[tid] = loc; __syncthreads();
    for (int d = 128; d > 0; d >>= 1) {
        if (tid < d) ssum[tid] += ssum[tid + d];
        __syncthreads();
    }
    if (tid == 0) atomicAdd(&g_sumexp, ssum[0]);
    if (tid < 64 && hist[tid]) atomicAdd(&g_bcnt[tid], hist[tid]);
}

// 32 threads (= 32 half2 channel pairs), 64 nodes/block. BN3 + ReLU on read.
__global__ void k_pool(const void* __restrict__ batch, const float* __restrict__ x,
                       const __half2* __restrict__ y16,
                       const float* __restrict__ stats,
                       const float* __restrict__ gam, const float* __restrict__ bet,
                       float invn, int n) {
    __shared__ float w[64];
    __shared__ int bb[64];
    __shared__ float2 sscsh[64];   // [c2] = (sc, sh) per channel
    int tid = threadIdx.x;         // 0..31
    int base = blockIdx.x * 64;
    float S = g_sumexp;
    for (int j = tid; j < 64; j += 32) {
        int i = base + j;
        if (i < n) { w[j] = expf(__ldg(&x[i * 6 + 4])) / S; bb[j] = load_idx(batch, i); }
        else { w[j] = 0.f; bb[j] = -1; }
        // channels 2j? no: compute BN consts for channels j and j+32
        float mu = stats[j] * invn;
        float var = stats[64 + j] * invn - mu * mu;
        float rstd = rsqrtf(var + 1e-5f);
        float sc = rstd * gam[j];
        sscsh[j] = make_float2(sc, bet[j] - mu * sc);
    }
    __syncthreads();
    int c0 = tid * 2;
    float2 p0 = sscsh[c0], p1 = sscsh[c0 + 1];
    int m = n - base; if (m > 64) m = 64;
#define BNV(f) make_float2(fmaxf(fmaf((f).x, p0.x, p0.y), 0.f), fmaxf(fmaf((f).y, p1.x, p1.y), 0.f))
    if (m == 64 && bb[0] == bb[63]) {
        float ax0 = 0.f, ay0 = 0.f, ax1 = 0.f, ay1 = 0.f;
        float ax2 = 0.f, ay2 = 0.f, ax3 = 0.f, ay3 = 0.f;
        for (int j = 0; j < 64; j += 4) {
            float2 f0 = BNV(__half22float2(__ldg(&y16[(base + j + 0) * 32 + tid])));
            float2 f1 = BNV(__half22float2(__ldg(&y16[(base + j + 1) * 32 + tid])));
            float2 f2 = BNV(__half22float2(__ldg(&y16[(base + j + 2) * 32 + tid])));
            float2 f3 = BNV(__half22float2(__ldg(&y16[(base + j + 3) * 32 + tid])));
            ax0 += w[j] * f0.x;     ay0 += w[j] * f0.y;
            ax1 += w[j + 1] * f1.x; ay1 += w[j + 1] * f1.y;
            ax2 += w[j + 2] * f2.x; ay2 += w[j + 2] * f2.y;
            ax3 += w[j + 3] * f3.x; ay3 += w[j + 3] * f3.y;
        }
        atomicAdd(&g_pool[bb[0] * 64 + c0],     (ax0 + ax1) + (ax2 + ax3));
        atomicAdd(&g_pool[bb[0] * 64 + c0 + 1], (ay0 + ay1) + (ay2 + ay3));
    } else {
        float accx = 0.f, accy = 0.f;
        int cur = bb[0];
        for (int j = 0; j < m; j++) {
            int b = bb[j];
            if (b != cur) {
                if (cur >= 0) {
                    atomicAdd(&g_pool[cur * 64 + c0], accx);
                    atomicAdd(&g_pool[cur * 64 + c0 + 1], accy);
                }
                accx = 0.f; accy = 0.f; cur = b;
            }
            float2 f = BNV(__half22float2(__ldg(&y16[(base + j) * 32 + tid])));
            accx += w[j] * f.x; accy += w[j] * f.y;
        }
        if (cur >= 0 && m > 0) {
            atomicAdd(&g_pool[cur * 64 + c0], accx);
            atomicAdd(&g_pool[cur * 64 + c0 + 1], accy);
        }
    }
#undef BNV
}

// ---------------- heads ----------------
__global__ void k_head(const float* __restrict__ phW1, const float* __restrict__ phb1,
                       const float* __restrict__ phW2, const float* __restrict__ phb2,
                       const float* __restrict__ trW1, const float* __restrict__ trb1,
                       const float* __restrict__ trW2, const float* __restrict__ trb2,
                       float* __restrict__ out) {
    __shared__ float pool[64 * 64];
    __shared__ float hid[64 * 32];
    __shared__ float hidt[64 * 16];
    int tid = threadIdx.x;
    for (int i = tid; i < 64 * 64; i += 256) {
        int b = i >> 6;
        float c = (float)g_bcnt[b];
        pool[i] = g_pool[i] / fmaxf(c, 1.f);
    }
    __syncthreads();
    for (int i = tid; i < 64 * 32; i += 256) {
        int b = i >> 5, j = i & 31;
        float s = phb1[j];
        for (int k = 0; k < 64; k++) s += pool[b * 64 + k] * phW1[k * 32 + j];
        hid[i] = fmaxf(s, 0.f);
    }
    for (int i = tid; i < 64 * 16; i += 256) {
        int b = i >> 4, j = i & 15;
        float s = trb1[j];
        for (int k = 0; k < 64; k++) s += pool[b * 64 + k] * trW1[k * 16 + j];
        hidt[i] = fmaxf(s, 0.f);
    }
    __syncthreads();
    for (int i = tid; i < 64 * 3; i += 256) {
        int b = i / 3, j = i - b * 3;
        float s = phb2[j];
        for (int k = 0; k < 32; k++) s += hid[b * 32 + k] * phW2[k * 3 + j];
        out[i] = s;
    }
    for (int i = tid; i < 64; i += 256) {
        float s = trb2[0];
        for (int k = 0; k < 16; k++) s += hidt[i * 16 + k] * trW2[k];
        out[192 + i] = 1.f / (1.f + expf(-s));
    }
}

// ---------------- launch ----------------
extern "C" void kernel_launch(void* const* d_in, const int* in_sizes, int n_in,
                              void* d_out, int out_size) {
    const float* x   = (const float*)d_in[0];
    const void*  ei  = d_in[1];
    const void*  bat = d_in[2];
    const float* W1l = (const float*)d_in[3];
    const float* b1  = (const float*)d_in[4];
    const float* W1r = (const float*)d_in[5];
    const float* W2l = (const float*)d_in[6];
    const float* b2  = (const float*)d_in[7];
    const float* W2r = (const float*)d_in[8];
    const float* W3l = (const float*)d_in[9];
    const float* b3  = (const float*)d_in[10];
    const float* W3r = (const float*)d_in[11];
    const float* g1  = (const float*)d_in[12];
    const float* be1 = (const float*)d_in[13];
    const float* g2  = (const float*)d_in[14];
    const float* be2 = (const float*)d_in[15];
    const float* g3  = (const float*)d_in[16];
    const float* be3 = (const float*)d_in[17];
    const float* phW1 = (const float*)d_in[18];
    const float* phb1 = (const float*)d_in[19];
    const float* phW2 = (const float*)d_in[20];
    const float* phb2 = (const float*)d_in[21];
    const float* trW1 = (const float*)d_in[22];
    const float* trb1 = (const float*)d_in[23];
    const float* trW2 = (const float*)d_in[24];
    const float* trb2 = (const float*)d_in[25];
    float* out = (float*)d_out;

    int n = in_sizes[0] / 6;
    int e = in_sizes[1] / 2;

    float *p_agg, *p_agg6, *p_hself, *p_stats;
    __half2 *p_ya, *p_yb;
    cudaGetSymbolAddress((void**)&p_agg, g_agg);
    cudaGetSymbolAddress((void**)&p_agg6, g_agg6);
    cudaGetSymbolAddress((void**)&p_hself, g_hself);
    cudaGetSymbolAddress((void**)&p_stats, g_stats);
    cudaGetSymbolAddress((void**)&p_ya, g_y16a);
    cudaGetSymbolAddress((void**)&p_yb, g_y16b);

    // init + CSR
    k_init<<<(n + 255) / 256, 256>>>((const long long*)ei, n);
    k_hist<<<(e + 255) / 256, 256>>>(ei, e);
    int nb = (n + 1023) / 1024;
    k_scan1<<<nb, 1024>>>(n);
    k_scan2<<<1, 1024>>>(nb, n, e);
    k_scan3<<<nb, 1024>>>(n);
    k_scatter<<<(e + 255) / 256, 256>>>(ei, e);

    int aggBlocks = (n * 32 + 255) / 256;
    int mmBlocks = (n + 63) / 64;
    int nodeBlocks = (n + 63) / 64;
    float invn = 1.f / (float)n;

    // layer 1: agg(x) ; y1 = agg@W1l + x@W1r + b1  -> fp16
    k_agg6<<<aggBlocks, 256>>>(x, n);
    k_mm<6, 8, 6><<<mmBlocks, 256>>>(p_agg6, x, W1l, W1r, b1, p_ya, p_stats + 0 * 128, n);

    // layer 2: gather BN1(y1), self BN1(y1) ; y2 -> fp16
    k_agg64h<<<aggBlocks, 256>>>(p_ya, p_stats + 0 * 128, g1, be1, invn, p_agg, p_hself, n);
    k_mm<64, 64, 64><<<mmBlocks, 256>>>(p_agg, p_hself, W2l, W2r, b2, p_yb, p_stats + 1 * 128, n);

    // layer 3: gather BN2(y2), self BN2(y2) ; y3 -> fp16 (reuse ya)
    k_agg64h<<<aggBlocks, 256>>>(p_yb, p_stats + 1 * 128, g2, be2, invn, p_agg, p_hself, n);
    k_mm<64, 64, 64><<<mmBlocks, 256>>>(p_agg, p_hself, W3l, W3r, b3, p_ya, p_stats + 2 * 128, n);

    // pooling (BN3 on read) + heads
    k_prepool<<<(n + 255) / 256, 256>>>(x, bat, n);
    k_pool<<<nodeBlocks, 32>>>(bat, x, p_ya, p_stats + 2 * 128, g3, be3, invn, n);
    k_head<<<1, 256>>>(phW1, phb1, phW2, phb2, trW1, trb1, trW2, trb2, out);
}